// round 10
// baseline (speedup 1.0000x reference)
#include <cuda_runtime.h>
#include <cstdint>

// CausalConv1d: x (4, 2048, 8192) f32, depthwise weight (2048, 1, 16), bias (2048)
// out[n,c,l] = sum_{k=0..15} x[n,c,l-15+k] * w[c,0,k] + bias[c]   (zero-pad left)
//
// R6 pipeline at half-row granularity: one block per half-row (4096 outputs,
// 4 stages of 1024). tid 0 bursts all 4 cp.async.bulk tiles up front
// (per-stage complete_tx mbarrier); consumers do 5 conflict-free LDS.128 +
// 64 FMA + STG.128 per stage. Halving the work quantum halves the
// wave-quantization tail (grid 16384, ~22 waves of 740 resident blocks).

#define DIM    2048
#define LEN    8192
#define KSZ    16
#define BLOCK  256
#define OPT    4
#define TILE   (BLOCK * OPT)      // 1024
#define NST    4                  // stages per half-row
#define HALF   (NST * TILE)       // 4096
#define STAGEF (TILE + KSZ)       // 1040 floats per stage
#define STAGEB (STAGEF * 4)       // 4160 bytes

__device__ __forceinline__ uint32_t smem_u32(const void* p) {
    return (uint32_t)__cvta_generic_to_shared(p);
}

__device__ __forceinline__ void mbar_init(uint32_t mbar, uint32_t count) {
    asm volatile("mbarrier.init.shared.b64 [%0], %1;" :: "r"(mbar), "r"(count) : "memory");
}

__device__ __forceinline__ void mbar_expect_tx(uint32_t mbar, uint32_t bytes) {
    asm volatile("mbarrier.arrive.expect_tx.shared.b64 _, [%0], %1;"
                 :: "r"(mbar), "r"(bytes) : "memory");
}

__device__ __forceinline__ void bulk_g2s(uint32_t dst, const void* src,
                                         uint32_t bytes, uint32_t mbar) {
    asm volatile(
        "cp.async.bulk.shared::cta.global.mbarrier::complete_tx::bytes [%0], [%1], %2, [%3];"
        :: "r"(dst), "l"(src), "r"(bytes), "r"(mbar) : "memory");
}

__device__ __forceinline__ void mbar_wait_parity0(uint32_t mbar) {
    uint32_t done;
    asm volatile(
        "{\n\t.reg .pred p;\n\t"
        "mbarrier.try_wait.parity.acquire.cta.shared::cta.b64 p, [%1], 0;\n\t"
        "selp.b32 %0, 1, 0, p;\n\t}"
        : "=r"(done) : "r"(mbar) : "memory");
    if (!done) {
        asm volatile(
            "{\n\t.reg .pred P1;\n\t"
            "WAIT_LOOP_%=:\n\t"
            "mbarrier.try_wait.parity.acquire.cta.shared::cta.b64 P1, [%0], 0, 0x989680;\n\t"
            "@P1 bra.uni WAIT_DONE_%=;\n\t"
            "bra.uni WAIT_LOOP_%=;\n\t"
            "WAIT_DONE_%=:\n\t}"
            :: "r"(mbar) : "memory");
    }
}

__global__ __launch_bounds__(BLOCK, 5) void causal_conv1d_kernel(
    const float* __restrict__ x,
    const float* __restrict__ w,
    const float* __restrict__ bias,
    float* __restrict__ out)
{
    __shared__ alignas(128) float stage[NST][STAGEF];
    __shared__ alignas(8)   unsigned long long mbar[NST];

    const int tid  = threadIdx.x;
    const int row  = blockIdx.x >> 1;
    const int half = blockIdx.x & 1;
    const int ch   = row & (DIM - 1);            // row = n*DIM + c

    const float* __restrict__ xrow = x   + (size_t)row * LEN;
    float*       __restrict__ orow = out + (size_t)row * LEN;

    const int h0 = half * HALF;                  // first output index of this block

    // ---- init barriers + zero the 16-float left pad of stage 0 (only used
    //      when h0 == 0; harmless otherwise since that slot gets overwritten) ----
    if (tid < NST) mbar_init(smem_u32(&mbar[tid]), 1);
    if (tid < KSZ / 4) {
        float4 z = make_float4(0.f, 0.f, 0.f, 0.f);
        *reinterpret_cast<float4*>(&stage[0][4 * tid]) = z;
    }
    __syncthreads();

    // ---- producer: prefetch all 4 stages immediately (tid 0) ----
    if (tid == 0) {
        asm volatile("fence.proxy.async.shared::cta;" ::: "memory");
        if (h0 == 0) {
            // stage 0 at row start: data lands at offset 16, halo is the zero pad
            mbar_expect_tx(smem_u32(&mbar[0]), TILE * 4);
            bulk_g2s(smem_u32(&stage[0][KSZ]), xrow, TILE * 4, smem_u32(&mbar[0]));
        } else {
            mbar_expect_tx(smem_u32(&mbar[0]), STAGEB);
            bulk_g2s(smem_u32(&stage[0][0]), xrow + h0 - KSZ, STAGEB, smem_u32(&mbar[0]));
        }
        #pragma unroll
        for (int s = 1; s < NST; s++) {
            mbar_expect_tx(smem_u32(&mbar[s]), STAGEB);
            bulk_g2s(smem_u32(&stage[s][0]), xrow + h0 + s * TILE - KSZ,
                     STAGEB, smem_u32(&mbar[s]));
        }
    }

    // ---- weights + bias (warp-uniform, overlaps TMA) ----
    float wr[KSZ];
    const float4* w4 = reinterpret_cast<const float4*>(w + ch * KSZ);
    #pragma unroll
    for (int q = 0; q < 4; q++) {
        float4 t = w4[q];
        wr[4 * q + 0] = t.x; wr[4 * q + 1] = t.y;
        wr[4 * q + 2] = t.z; wr[4 * q + 3] = t.w;
    }
    const float b = bias[ch];

    // ---- consume stage by stage ----
    #pragma unroll
    for (int s = 0; s < NST; s++) {
        mbar_wait_parity0(smem_u32(&mbar[s]));

        // window r[i] = xrow[h0 + s*TILE - 16 + 4*tid + i] = stage[s][4*tid + i]
        float r[OPT + KSZ];
        const float4* sp = reinterpret_cast<const float4*>(&stage[s][4 * tid]);
        #pragma unroll
        for (int q = 0; q < 5; q++) {
            float4 v = sp[q];
            r[4 * q + 0] = v.x; r[4 * q + 1] = v.y;
            r[4 * q + 2] = v.z; r[4 * q + 3] = v.w;
        }

        float acc[OPT];
        #pragma unroll
        for (int m = 0; m < OPT; m++) {
            float a = b;
            #pragma unroll
            for (int k = 0; k < KSZ; k++)
                a = fmaf(wr[k], r[m + 1 + k], a);
            acc[m] = a;
        }

        float4 o; o.x = acc[0]; o.y = acc[1]; o.z = acc[2]; o.w = acc[3];
        *reinterpret_cast<float4*>(orow + h0 + s * TILE + 4 * tid) = o;
    }
}

extern "C" void kernel_launch(void* const* d_in, const int* in_sizes, int n_in,
                              void* d_out, int out_size)
{
    const float* x    = (const float*)d_in[0];
    const float* w    = (const float*)d_in[1];
    const float* bias = (const float*)d_in[2];
    float* out        = (float*)d_out;

    const int blocks = 4 * DIM * 2;              // 16384 half-rows
    causal_conv1d_kernel<<<blocks, BLOCK>>>(x, w, bias, out);
}

// round 11
// speedup vs baseline: 1.0065x; 1.0065x over previous
#include <cuda_runtime.h>
#include <cstdint>

// CausalConv1d: x (4, 2048, 8192) f32, depthwise weight (2048, 1, 16), bias (2048)
// out[n,c,l] = sum_{k=0..15} x[n,c,l-15+k] * w[c,0,k] + bias[c]   (zero-pad left)
//
// R9 structure (best ncu: 76.1us): one block per row, tid 0 bursts all 8
// cp.async.bulk tiles up front (per-stage complete_tx mbarrier), consumers do
// 5 conflict-free LDS.128 + 64 FMA + STG.128 per stage. This round: force
// 6 blocks/SM (reg cap 42, smem 200KB/228KB) for +20% warps and +20%
// concurrent TMA streams to close the exposed-latency gap.

#define DIM    2048
#define LEN    8192
#define KSZ    16
#define BLOCK  256
#define OPT    4
#define TILE   (BLOCK * OPT)      // 1024
#define NST    (LEN / TILE)       // 8 stages
#define STAGEF (TILE + KSZ)       // 1040 floats per stage
#define STAGEB (STAGEF * 4)       // 4160 bytes

__device__ __forceinline__ uint32_t smem_u32(const void* p) {
    return (uint32_t)__cvta_generic_to_shared(p);
}

__device__ __forceinline__ void mbar_init(uint32_t mbar, uint32_t count) {
    asm volatile("mbarrier.init.shared.b64 [%0], %1;" :: "r"(mbar), "r"(count) : "memory");
}

__device__ __forceinline__ void mbar_expect_tx(uint32_t mbar, uint32_t bytes) {
    asm volatile("mbarrier.arrive.expect_tx.shared.b64 _, [%0], %1;"
                 :: "r"(mbar), "r"(bytes) : "memory");
}

__device__ __forceinline__ void bulk_g2s(uint32_t dst, const void* src,
                                         uint32_t bytes, uint32_t mbar) {
    asm volatile(
        "cp.async.bulk.shared::cta.global.mbarrier::complete_tx::bytes [%0], [%1], %2, [%3];"
        :: "r"(dst), "l"(src), "r"(bytes), "r"(mbar) : "memory");
}

__device__ __forceinline__ void mbar_wait_parity0(uint32_t mbar) {
    uint32_t done;
    asm volatile(
        "{\n\t.reg .pred p;\n\t"
        "mbarrier.try_wait.parity.acquire.cta.shared::cta.b64 p, [%1], 0;\n\t"
        "selp.b32 %0, 1, 0, p;\n\t}"
        : "=r"(done) : "r"(mbar) : "memory");
    if (!done) {
        asm volatile(
            "{\n\t.reg .pred P1;\n\t"
            "WAIT_LOOP_%=:\n\t"
            "mbarrier.try_wait.parity.acquire.cta.shared::cta.b64 P1, [%0], 0, 0x989680;\n\t"
            "@P1 bra.uni WAIT_DONE_%=;\n\t"
            "bra.uni WAIT_LOOP_%=;\n\t"
            "WAIT_DONE_%=:\n\t}"
            :: "r"(mbar) : "memory");
    }
}

__global__ __launch_bounds__(BLOCK, 6) void causal_conv1d_kernel(
    const float* __restrict__ x,
    const float* __restrict__ w,
    const float* __restrict__ bias,
    float* __restrict__ out)
{
    __shared__ alignas(128) float stage[NST][STAGEF];
    __shared__ alignas(8)   unsigned long long mbar[NST];

    const int tid = threadIdx.x;
    const int row = blockIdx.x;
    const int ch  = row & (DIM - 1);             // row = n*DIM + c

    const float* __restrict__ xrow = x   + (size_t)row * LEN;
    float*       __restrict__ orow = out + (size_t)row * LEN;

    // ---- init barriers + zero the 16-float left pad of stage 0 ----
    if (tid < NST) mbar_init(smem_u32(&mbar[tid]), 1);
    if (tid < KSZ / 4) {
        float4 z = make_float4(0.f, 0.f, 0.f, 0.f);
        *reinterpret_cast<float4*>(&stage[0][4 * tid]) = z;
    }
    __syncthreads();

    // ---- producer: prefetch all 8 stages immediately (tid 0) ----
    if (tid == 0) {
        asm volatile("fence.proxy.async.shared::cta;" ::: "memory");
        // stage 0: data starts at offset 16 (halo is the zero pad)
        mbar_expect_tx(smem_u32(&mbar[0]), TILE * 4);
        bulk_g2s(smem_u32(&stage[0][KSZ]), xrow, TILE * 4, smem_u32(&mbar[0]));
        #pragma unroll
        for (int s = 1; s < NST; s++) {
            mbar_expect_tx(smem_u32(&mbar[s]), STAGEB);
            bulk_g2s(smem_u32(&stage[s][0]), xrow + s * TILE - KSZ,
                     STAGEB, smem_u32(&mbar[s]));
        }
    }

    // ---- weights + bias (warp-uniform, overlaps TMA) ----
    float wr[KSZ];
    const float4* w4 = reinterpret_cast<const float4*>(w + ch * KSZ);
    #pragma unroll
    for (int q = 0; q < 4; q++) {
        float4 t = w4[q];
        wr[4 * q + 0] = t.x; wr[4 * q + 1] = t.y;
        wr[4 * q + 2] = t.z; wr[4 * q + 3] = t.w;
    }
    const float b = bias[ch];

    // ---- consume stage by stage ----
    #pragma unroll
    for (int s = 0; s < NST; s++) {
        mbar_wait_parity0(smem_u32(&mbar[s]));

        // window r[i] = xrow[s*TILE - 16 + 4*tid + i] = stage[s][4*tid + i]
        float r[OPT + KSZ];
        const float4* sp = reinterpret_cast<const float4*>(&stage[s][4 * tid]);
        #pragma unroll
        for (int q = 0; q < 5; q++) {
            float4 v = sp[q];
            r[4 * q + 0] = v.x; r[4 * q + 1] = v.y;
            r[4 * q + 2] = v.z; r[4 * q + 3] = v.w;
        }

        float acc[OPT];
        #pragma unroll
        for (int m = 0; m < OPT; m++) {
            float a = b;
            #pragma unroll
            for (int k = 0; k < KSZ; k++)
                a = fmaf(wr[k], r[m + 1 + k], a);
            acc[m] = a;
        }

        float4 o; o.x = acc[0]; o.y = acc[1]; o.z = acc[2]; o.w = acc[3];
        *reinterpret_cast<float4*>(orow + s * TILE + 4 * tid) = o;
    }
}

extern "C" void kernel_launch(void* const* d_in, const int* in_sizes, int n_in,
                              void* d_out, int out_size)
{
    const float* x    = (const float*)d_in[0];
    const float* w    = (const float*)d_in[1];
    const float* bias = (const float*)d_in[2];
    float* out        = (float*)d_out;

    const int blocks = 4 * DIM;                  // 8192 rows
    causal_conv1d_kernel<<<blocks, BLOCK>>>(x, w, bias, out);
}

// round 12
// speedup vs baseline: 1.0260x; 1.0194x over previous
#include <cuda_runtime.h>
#include <cstdint>

// CausalConv1d: x (4, 2048, 8192) f32, depthwise weight (2048, 1, 16), bias (2048)
// out[n,c,l] = sum_{k=0..15} x[n,c,l-15+k] * w[c,0,k] + bias[c]   (zero-pad left)
//
// At the HBM floor (~6.3 TB/s, 1:1 R/W stream). R9 structure: one block per
// row, all 8 cp.async.bulk tiles prefetched up front, consumers do 5
// conflict-free LDS.128 + 64 FMA + store per stage. Refinements this round:
//  - lane 0 of warp s issues stage s's TMA (parallel prologue, no serial chain)
//  - st.global.cs streaming stores (output has zero reuse)
//  - launch_bounds(256,5): the best-measured residency/reg tradeoff

#define DIM    2048
#define LEN    8192
#define KSZ    16
#define BLOCK  256
#define OPT    4
#define TILE   (BLOCK * OPT)      // 1024
#define NST    (LEN / TILE)       // 8 stages
#define STAGEF (TILE + KSZ)       // 1040 floats per stage
#define STAGEB (STAGEF * 4)       // 4160 bytes

__device__ __forceinline__ uint32_t smem_u32(const void* p) {
    return (uint32_t)__cvta_generic_to_shared(p);
}

__device__ __forceinline__ void mbar_init(uint32_t mbar, uint32_t count) {
    asm volatile("mbarrier.init.shared.b64 [%0], %1;" :: "r"(mbar), "r"(count) : "memory");
}

__device__ __forceinline__ void mbar_expect_tx(uint32_t mbar, uint32_t bytes) {
    asm volatile("mbarrier.arrive.expect_tx.shared.b64 _, [%0], %1;"
                 :: "r"(mbar), "r"(bytes) : "memory");
}

__device__ __forceinline__ void bulk_g2s(uint32_t dst, const void* src,
                                         uint32_t bytes, uint32_t mbar) {
    asm volatile(
        "cp.async.bulk.shared::cta.global.mbarrier::complete_tx::bytes [%0], [%1], %2, [%3];"
        :: "r"(dst), "l"(src), "r"(bytes), "r"(mbar) : "memory");
}

__device__ __forceinline__ void mbar_wait_parity0(uint32_t mbar) {
    uint32_t done;
    asm volatile(
        "{\n\t.reg .pred p;\n\t"
        "mbarrier.try_wait.parity.acquire.cta.shared::cta.b64 p, [%1], 0;\n\t"
        "selp.b32 %0, 1, 0, p;\n\t}"
        : "=r"(done) : "r"(mbar) : "memory");
    if (!done) {
        asm volatile(
            "{\n\t.reg .pred P1;\n\t"
            "WAIT_LOOP_%=:\n\t"
            "mbarrier.try_wait.parity.acquire.cta.shared::cta.b64 P1, [%0], 0, 0x989680;\n\t"
            "@P1 bra.uni WAIT_DONE_%=;\n\t"
            "bra.uni WAIT_LOOP_%=;\n\t"
            "WAIT_DONE_%=:\n\t}"
            :: "r"(mbar) : "memory");
    }
}

__device__ __forceinline__ void stg_cs_v4(float* p, float a, float b, float c, float d) {
    asm volatile("st.global.cs.v4.f32 [%0], {%1, %2, %3, %4};"
                 :: "l"(p), "f"(a), "f"(b), "f"(c), "f"(d) : "memory");
}

__global__ __launch_bounds__(BLOCK, 5) void causal_conv1d_kernel(
    const float* __restrict__ x,
    const float* __restrict__ w,
    const float* __restrict__ bias,
    float* __restrict__ out)
{
    __shared__ alignas(128) float stage[NST][STAGEF];
    __shared__ alignas(8)   unsigned long long mbar[NST];

    const int tid  = threadIdx.x;
    const int wid  = tid >> 5;
    const int lane = tid & 31;
    const int row  = blockIdx.x;
    const int ch   = row & (DIM - 1);            // row = n*DIM + c

    const float* __restrict__ xrow = x   + (size_t)row * LEN;
    float*       __restrict__ orow = out + (size_t)row * LEN;

    // ---- init barriers + zero the 16-float left pad of stage 0 ----
    if (tid < NST) mbar_init(smem_u32(&mbar[tid]), 1);
    if (tid < KSZ / 4) {
        float4 z = make_float4(0.f, 0.f, 0.f, 0.f);
        *reinterpret_cast<float4*>(&stage[0][4 * tid]) = z;
    }
    __syncthreads();

    // ---- producer: lane 0 of warp s issues stage s (parallel prologue) ----
    if (lane == 0) {
        asm volatile("fence.proxy.async.shared::cta;" ::: "memory");
        const int s = wid;
        if (s == 0) {
            // stage 0: data lands at offset 16 (halo is the zero pad)
            mbar_expect_tx(smem_u32(&mbar[0]), TILE * 4);
            bulk_g2s(smem_u32(&stage[0][KSZ]), xrow, TILE * 4, smem_u32(&mbar[0]));
        } else {
            mbar_expect_tx(smem_u32(&mbar[s]), STAGEB);
            bulk_g2s(smem_u32(&stage[s][0]), xrow + s * TILE - KSZ,
                     STAGEB, smem_u32(&mbar[s]));
        }
    }

    // ---- weights + bias (warp-uniform, overlaps TMA) ----
    float wr[KSZ];
    const float4* w4 = reinterpret_cast<const float4*>(w + ch * KSZ);
    #pragma unroll
    for (int q = 0; q < 4; q++) {
        float4 t = w4[q];
        wr[4 * q + 0] = t.x; wr[4 * q + 1] = t.y;
        wr[4 * q + 2] = t.z; wr[4 * q + 3] = t.w;
    }
    const float b = bias[ch];

    // ---- consume stage by stage ----
    #pragma unroll
    for (int s = 0; s < NST; s++) {
        mbar_wait_parity0(smem_u32(&mbar[s]));

        // window r[i] = xrow[s*TILE - 16 + 4*tid + i] = stage[s][4*tid + i]
        float r[OPT + KSZ];
        const float4* sp = reinterpret_cast<const float4*>(&stage[s][4 * tid]);
        #pragma unroll
        for (int q = 0; q < 5; q++) {
            float4 v = sp[q];
            r[4 * q + 0] = v.x; r[4 * q + 1] = v.y;
            r[4 * q + 2] = v.z; r[4 * q + 3] = v.w;
        }

        float acc[OPT];
        #pragma unroll
        for (int m = 0; m < OPT; m++) {
            float a = b;
            #pragma unroll
            for (int k = 0; k < KSZ; k++)
                a = fmaf(wr[k], r[m + 1 + k], a);
            acc[m] = a;
        }

        stg_cs_v4(orow + s * TILE + 4 * tid, acc[0], acc[1], acc[2], acc[3]);
    }
}

extern "C" void kernel_launch(void* const* d_in, const int* in_sizes, int n_in,
                              void* d_out, int out_size)
{
    const float* x    = (const float*)d_in[0];
    const float* w    = (const float*)d_in[1];
    const float* bias = (const float*)d_in[2];
    float* out        = (float*)d_out;

    const int blocks = 4 * DIM;                  // 8192 rows
    causal_conv1d_kernel<<<blocks, BLOCK>>>(x, w, bias, out);
}